// round 2
// baseline (speedup 1.0000x reference)
#include <cuda_runtime.h>
#include <math.h>

#define D_MODEL 256
#define NHEAD   8
#define HEADDIM 32
#define NQ      100
#define MAX_TOK 65536
#define MAX_BNQ 1600

typedef unsigned long long u64;

// ---------------- packed f32x2 helpers (Blackwell FFMA2 path) ---------------
__device__ __forceinline__ u64 pack2(float lo, float hi) {
    u64 r; asm("mov.b64 %0, {%1, %2};" : "=l"(r) : "f"(lo), "f"(hi)); return r;
}
__device__ __forceinline__ float2 unpack2(u64 v) {
    float2 r; asm("mov.b64 {%0, %1}, %2;" : "=f"(r.x), "=f"(r.y) : "l"(v)); return r;
}
__device__ __forceinline__ void fma2(u64 &d, u64 a, u64 b) {
    asm("fma.rn.f32x2 %0, %1, %2, %0;" : "+l"(d) : "l"(a), "l"(b));
}
__device__ __forceinline__ u64 add2(u64 a, u64 b) {
    u64 r; asm("add.rn.f32x2 %0, %1, %2;" : "=l"(r) : "l"(a), "l"(b)); return r;
}
__device__ __forceinline__ u64 mul2(u64 a, u64 b) {
    u64 r; asm("mul.rn.f32x2 %0, %1, %2;" : "=l"(r) : "l"(a), "l"(b)); return r;
}

// ---------------- scratch ----------------------------------------------------
__device__ float g_K[(size_t)MAX_TOK * D_MODEL];
__device__ float g_V[(size_t)MAX_TOK * D_MODEL];
__device__ float g_Qs[(size_t)MAX_BNQ * D_MODEL];
__device__ float g_ctx[(size_t)MAX_BNQ * D_MODEL];

// ---------------- GEMM: C = (A @ W^T + bias) * scale (+ res) ----------------
// 128x128 block tile, BK=32, 256 threads, 8x8 microtile on FFMA2 (pairs on M).
#define BK 32

__global__ __launch_bounds__(256)
void gemm_bias_kernel(const float* __restrict__ A, const float* __restrict__ W,
                      const float* __restrict__ bias, const float* __restrict__ res,
                      float* __restrict__ C, int M, int N, int K,
                      float scale, int add_res)
{
    __shared__ float As[BK][132];
    __shared__ float Ws[BK][132];

    const int m0 = blockIdx.y * 128;
    const int n0 = blockIdx.x * 128;
    const int t  = threadIdx.x;
    const int tx = t & 15;
    const int ty = t >> 4;

    u64 acc[4][8];
#pragma unroll
    for (int i = 0; i < 4; i++)
#pragma unroll
        for (int j = 0; j < 8; j++) acc[i][j] = 0ull;

    for (int k0 = 0; k0 < K; k0 += BK) {
#pragma unroll
        for (int r = 0; r < 4; r++) {
            int idx = t + r * 256;           // 0..1023
            int row = idx >> 3;              // 0..127
            int cg  = (idx & 7) * 4;         // 0..28
            int gm  = m0 + row;
            int gn  = n0 + row;
            float4 va = make_float4(0.f, 0.f, 0.f, 0.f);
            float4 vw = make_float4(0.f, 0.f, 0.f, 0.f);
            if (gm < M) va = *(const float4*)(A + (size_t)gm * K + k0 + cg);
            if (gn < N) vw = *(const float4*)(W + (size_t)gn * K + k0 + cg);
            As[cg + 0][row] = va.x; As[cg + 1][row] = va.y;
            As[cg + 2][row] = va.z; As[cg + 3][row] = va.w;
            Ws[cg + 0][row] = vw.x; Ws[cg + 1][row] = vw.y;
            Ws[cg + 2][row] = vw.z; Ws[cg + 3][row] = vw.w;
        }
        __syncthreads();

#pragma unroll
        for (int kk = 0; kk < BK; kk++) {
            float4 a0 = *(const float4*)&As[kk][ty * 8];
            float4 a1 = *(const float4*)&As[kk][ty * 8 + 4];
            float4 w0 = *(const float4*)&Ws[kk][tx * 8];
            float4 w1 = *(const float4*)&Ws[kk][tx * 8 + 4];
            u64 ap0 = pack2(a0.x, a0.y), ap1 = pack2(a0.z, a0.w);
            u64 ap2 = pack2(a1.x, a1.y), ap3 = pack2(a1.z, a1.w);
            float wv[8] = {w0.x, w0.y, w0.z, w0.w, w1.x, w1.y, w1.z, w1.w};
#pragma unroll
            for (int j = 0; j < 8; j++) {
                u64 wd = pack2(wv[j], wv[j]);
                fma2(acc[0][j], ap0, wd);
                fma2(acc[1][j], ap1, wd);
                fma2(acc[2][j], ap2, wd);
                fma2(acc[3][j], ap3, wd);
            }
        }
        __syncthreads();
    }

#pragma unroll
    for (int ip = 0; ip < 4; ip++) {
        int gmA = m0 + ty * 8 + ip * 2;
        int gmB = gmA + 1;
#pragma unroll
        for (int j = 0; j < 8; j++) {
            int gn = n0 + tx * 8 + j;
            float2 v = unpack2(acc[ip][j]);
            if (gmA < M) {
                float r = (v.x + bias[gn]) * scale;
                if (add_res) r += res[(size_t)gmA * N + gn];
                C[(size_t)gmA * N + gn] = r;
            }
            if (gmB < M) {
                float r = (v.y + bias[gn]) * scale;
                if (add_res) r += res[(size_t)gmB * N + gn];
                C[(size_t)gmB * N + gn] = r;
            }
        }
    }
}

// ---------------- attention ------------------------------------------------
// Block = (32-query chunk, head, batch); 128 threads = 4 warps x 8 queries.
// lane == head-dim. Scores & PV on FFMA2; probs via smem (no PV shuffles).
__global__ __launch_bounds__(128)
void attn_kernel(const float* __restrict__ Qs, const float* __restrict__ Kg,
                 const float* __restrict__ Vg, const int* __restrict__ offs,
                 float* __restrict__ ctx)
{
    const int chunk = blockIdx.x;
    const int h     = blockIdx.y;
    const int b     = blockIdx.z;
    const int t     = threadIdx.x;
    const int w     = t >> 5;
    const int lane  = t & 31;

    __shared__ float qsT[HEADDIM][36];   // [dim][query] (pairs along q)
    __shared__ float Kt[HEADDIM][65];    // [dim][key]
    __shared__ float Vs[64][33];         // [key][dim]
    __shared__ u64   Pt[64][18];         // [key][qpair] packed probs

    const int off0 = offs[b];
    const int len  = offs[b + 1] - off0;

    // load Q chunk transposed
#pragma unroll
    for (int r = 0; r < 2; r++) {
        int idx = t + r * 128;
        int row = idx >> 3;              // q 0..31
        int cg  = (idx & 7) * 4;
        int nq  = chunk * 32 + row;
        float4 v = make_float4(0.f, 0.f, 0.f, 0.f);
        if (nq < NQ)
            v = *(const float4*)(Qs + ((size_t)(b * NQ + nq)) * D_MODEL + h * HEADDIM + cg);
        qsT[cg + 0][row] = v.x; qsT[cg + 1][row] = v.y;
        qsT[cg + 2][row] = v.z; qsT[cg + 3][row] = v.w;
    }

    u64 o2[4] = {0ull, 0ull, 0ull, 0ull};   // (q even, q odd) output pairs
    u64 lp[4] = {0ull, 0ull, 0ull, 0ull};   // per-lane l pairs
    float m[8];
#pragma unroll
    for (int q = 0; q < 8; q++) m[q] = -INFINITY;

    const int qrow = w * 8;
    const int qp0  = w * 4;

    for (int kt = 0; kt < len; kt += 64) {
        __syncthreads();
        // load K (transposed) and V tiles
#pragma unroll
        for (int r = 0; r < 4; r++) {
            int idx = t + r * 128;
            int row = idx >> 3;          // key 0..63
            int cg  = (idx & 7) * 4;
            int key = kt + row;
            float4 kv = make_float4(0.f, 0.f, 0.f, 0.f);
            float4 vv = make_float4(0.f, 0.f, 0.f, 0.f);
            if (key < len) {
                size_t base = ((size_t)(off0 + key)) * D_MODEL + h * HEADDIM + cg;
                kv = *(const float4*)(Kg + base);
                vv = *(const float4*)(Vg + base);
            }
            Kt[cg + 0][row] = kv.x; Kt[cg + 1][row] = kv.y;
            Kt[cg + 2][row] = kv.z; Kt[cg + 3][row] = kv.w;
            Vs[row][cg + 0] = vv.x; Vs[row][cg + 1] = vv.y;
            Vs[row][cg + 2] = vv.z; Vs[row][cg + 3] = vv.w;
        }
        __syncthreads();

        // ---- QK^T: s pairs over adjacent queries, keys = lane / lane+32 ----
        u64 s0p[4] = {0ull, 0ull, 0ull, 0ull};
        u64 s1p[4] = {0ull, 0ull, 0ull, 0ull};
#pragma unroll 8
        for (int d = 0; d < HEADDIM; d++) {
            float k0 = Kt[d][lane];
            float k1 = Kt[d][lane + 32];
            u64 k0d = pack2(k0, k0);
            u64 k1d = pack2(k1, k1);
            float4 qa = *(const float4*)&qsT[d][qrow];
            float4 qb = *(const float4*)&qsT[d][qrow + 4];
            u64 q0 = pack2(qa.x, qa.y), q1 = pack2(qa.z, qa.w);
            u64 q2 = pack2(qb.x, qb.y), q3 = pack2(qb.z, qb.w);
            fma2(s0p[0], q0, k0d); fma2(s0p[1], q1, k0d);
            fma2(s0p[2], q2, k0d); fma2(s0p[3], q3, k0d);
            fma2(s1p[0], q0, k1d); fma2(s1p[1], q1, k1d);
            fma2(s1p[2], q2, k1d); fma2(s1p[3], q3, k1d);
        }

        const bool valid0 = (kt + lane) < len;
        const bool valid1 = (kt + 32 + lane) < len;

        float s0[8], s1[8];
#pragma unroll
        for (int qp = 0; qp < 4; qp++) {
            float2 v0 = unpack2(s0p[qp]); s0[2 * qp] = v0.x; s0[2 * qp + 1] = v0.y;
            float2 v1 = unpack2(s1p[qp]); s1[2 * qp] = v1.x; s1[2 * qp + 1] = v1.y;
        }

        // ---- online softmax (only max needs a warp reduction) ----
        float p0[8], p1[8], alpha[8];
#pragma unroll
        for (int q = 0; q < 8; q++) {
            float a  = valid0 ? s0[q] : -INFINITY;
            float bb = valid1 ? s1[q] : -INFINITY;
            float mx = fmaxf(a, bb);
#pragma unroll
            for (int o = 16; o; o >>= 1)
                mx = fmaxf(mx, __shfl_xor_sync(0xffffffffu, mx, o));
            float m_new = fmaxf(m[q], mx);
            p0[q] = __expf(a - m_new);
            p1[q] = __expf(bb - m_new);
            alpha[q] = __expf(m[q] - m_new);
            m[q] = m_new;
        }

#pragma unroll
        for (int qp = 0; qp < 4; qp++) {
            u64 pp0 = pack2(p0[2 * qp], p0[2 * qp + 1]);
            u64 pp1 = pack2(p1[2 * qp], p1[2 * qp + 1]);
            Pt[lane][qp0 + qp]      = pp0;
            Pt[lane + 32][qp0 + qp] = pp1;
            u64 ap = pack2(alpha[2 * qp], alpha[2 * qp + 1]);
            u64 ps = add2(pp0, pp1);
            fma2(ps, lp[qp], ap);            // ps = lp*alpha + (p0+p1)
            lp[qp] = ps;
            o2[qp] = mul2(o2[qp], ap);       // rescale running output
        }
        __syncwarp();

        // ---- PV: o[qpair][dim=lane] += P[k][qpair] * V[k][lane] ----
#pragma unroll 8
        for (int k = 0; k < 64; k++) {
            float v = Vs[k][lane];
            u64 vd = pack2(v, v);
            ulonglong2 pA = *(const ulonglong2*)&Pt[k][qp0];
            ulonglong2 pB = *(const ulonglong2*)&Pt[k][qp0 + 2];
            fma2(o2[0], pA.x, vd);
            fma2(o2[1], pA.y, vd);
            fma2(o2[2], pB.x, vd);
            fma2(o2[3], pB.y, vd);
        }
    }

    // ---- finalize: reduce l across lanes, divide, store ----
#pragma unroll
    for (int qp = 0; qp < 4; qp++) {
        float2 ov = unpack2(o2[qp]);
        float2 lv = unpack2(lp[qp]);
        float la = lv.x, lb = lv.y;
#pragma unroll
        for (int o = 16; o; o >>= 1) {
            la += __shfl_xor_sync(0xffffffffu, la, o);
            lb += __shfl_xor_sync(0xffffffffu, lb, o);
        }
        int nq0 = chunk * 32 + qrow + 2 * qp;
        if (nq0 < NQ)
            ctx[((size_t)(b * NQ + nq0)) * D_MODEL + h * HEADDIM + lane] =
                (la > 0.f) ? ov.x / la : 0.f;
        if (nq0 + 1 < NQ)
            ctx[((size_t)(b * NQ + nq0 + 1)) * D_MODEL + h * HEADDIM + lane] =
                (lb > 0.f) ? ov.y / lb : 0.f;
    }
}

// ---------------- launch -----------------------------------------------------
extern "C" void kernel_launch(void* const* d_in, const int* in_sizes, int n_in,
                              void* d_out, int out_size)
{
    const float* source = (const float*)d_in[0];
    const float* query  = (const float*)d_in[1];
    const int*   offs   = (const int*)  d_in[2];
    const float* Wq = (const float*)d_in[3];  const float* bq = (const float*)d_in[4];
    const float* Wk = (const float*)d_in[5];  const float* bk = (const float*)d_in[6];
    const float* Wv = (const float*)d_in[7];  const float* bv = (const float*)d_in[8];
    const float* Wo = (const float*)d_in[9];  const float* bo = (const float*)d_in[10];
    float* out = (float*)d_out;

    const int Ntok = in_sizes[0] / D_MODEL;
    const int B    = in_sizes[1] / (NQ * D_MODEL);
    const int Mq   = B * NQ;
    const float scale = 1.0f / sqrtf((float)HEADDIM);

    float *pK, *pV, *pQs, *pCtx;
    cudaGetSymbolAddress((void**)&pK,  g_K);
    cudaGetSymbolAddress((void**)&pV,  g_V);
    cudaGetSymbolAddress((void**)&pQs, g_Qs);
    cudaGetSymbolAddress((void**)&pCtx, g_ctx);

    dim3 blk(256);

    { // q projection (scaled)
        dim3 grid(D_MODEL / 128, (Mq + 127) / 128);
        gemm_bias_kernel<<<grid, blk>>>(query, Wq, bq, nullptr, pQs,
                                        Mq, D_MODEL, D_MODEL, scale, 0);
    }
    { // K projection
        dim3 grid(D_MODEL / 128, (Ntok + 127) / 128);
        gemm_bias_kernel<<<grid, blk>>>(source, Wk, bk, nullptr, pK,
                                        Ntok, D_MODEL, D_MODEL, 1.0f, 0);
    }
    { // V projection
        dim3 grid(D_MODEL / 128, (Ntok + 127) / 128);
        gemm_bias_kernel<<<grid, blk>>>(source, Wv, bv, nullptr, pV,
                                        Ntok, D_MODEL, D_MODEL, 1.0f, 0);
    }
    { // attention
        dim3 grid((NQ + 31) / 32, NHEAD, B);
        attn_kernel<<<grid, 128>>>(pQs, pK, pV, offs, pCtx);
    }
    { // out projection + bias + residual
        dim3 grid(D_MODEL / 128, (Mq + 127) / 128);
        gemm_bias_kernel<<<grid, blk>>>(pCtx, Wo, bo, query, out,
                                        Mq, D_MODEL, D_MODEL, 1.0f, 1);
    }
}

// round 3
// speedup vs baseline: 1.0507x; 1.0507x over previous
#include <cuda_runtime.h>
#include <math.h>

#define D_MODEL 256
#define NHEAD   8
#define HEADDIM 32
#define NQ      100
#define MAX_TOK 65536
#define MAX_BNQ 1600

typedef unsigned long long u64;

// ---------------- packed f32x2 helpers (Blackwell FFMA2 path) ---------------
__device__ __forceinline__ u64 pack2(float lo, float hi) {
    u64 r; asm("mov.b64 %0, {%1, %2};" : "=l"(r) : "f"(lo), "f"(hi)); return r;
}
__device__ __forceinline__ float2 unpack2(u64 v) {
    float2 r; asm("mov.b64 {%0, %1}, %2;" : "=f"(r.x), "=f"(r.y) : "l"(v)); return r;
}
__device__ __forceinline__ void fma2(u64 &d, u64 a, u64 b) {
    asm("fma.rn.f32x2 %0, %1, %2, %0;" : "+l"(d) : "l"(a), "l"(b));
}
__device__ __forceinline__ u64 add2(u64 a, u64 b) {
    u64 r; asm("add.rn.f32x2 %0, %1, %2;" : "=l"(r) : "l"(a), "l"(b)); return r;
}
__device__ __forceinline__ u64 mul2(u64 a, u64 b) {
    u64 r; asm("mul.rn.f32x2 %0, %1, %2;" : "=l"(r) : "l"(a), "l"(b)); return r;
}

// ---------------- scratch ----------------------------------------------------
__device__ float g_K[(size_t)MAX_TOK * D_MODEL];
__device__ float g_V[(size_t)MAX_TOK * D_MODEL];
__device__ float g_Qs[(size_t)MAX_BNQ * D_MODEL];
__device__ float g_ctx[(size_t)MAX_BNQ * D_MODEL];

// ---------------- GEMM: C = (A @ W^T + bias) * scale (+ res) ----------------
// 128x128 block tile, BK=32, 256 threads, 8x8 microtile on FFMA2 (pairs on M).
#define BK 32

__global__ __launch_bounds__(256)
void gemm_bias_kernel(const float* __restrict__ A, const float* __restrict__ W,
                      const float* __restrict__ bias, const float* __restrict__ res,
                      float* __restrict__ C, int M, int N, int K,
                      float scale, int add_res)
{
    __shared__ float As[BK][132];
    __shared__ float Ws[BK][132];

    const int m0 = blockIdx.y * 128;
    const int n0 = blockIdx.x * 128;
    const int t  = threadIdx.x;
    const int tx = t & 15;
    const int ty = t >> 4;

    u64 acc[4][8];
#pragma unroll
    for (int i = 0; i < 4; i++)
#pragma unroll
        for (int j = 0; j < 8; j++) acc[i][j] = 0ull;

    for (int k0 = 0; k0 < K; k0 += BK) {
#pragma unroll
        for (int r = 0; r < 4; r++) {
            int idx = t + r * 256;           // 0..1023
            int row = idx >> 3;              // 0..127
            int cg  = (idx & 7) * 4;         // 0..28
            int gm  = m0 + row;
            int gn  = n0 + row;
            float4 va = make_float4(0.f, 0.f, 0.f, 0.f);
            float4 vw = make_float4(0.f, 0.f, 0.f, 0.f);
            if (gm < M) va = *(const float4*)(A + (size_t)gm * K + k0 + cg);
            if (gn < N) vw = *(const float4*)(W + (size_t)gn * K + k0 + cg);
            As[cg + 0][row] = va.x; As[cg + 1][row] = va.y;
            As[cg + 2][row] = va.z; As[cg + 3][row] = va.w;
            Ws[cg + 0][row] = vw.x; Ws[cg + 1][row] = vw.y;
            Ws[cg + 2][row] = vw.z; Ws[cg + 3][row] = vw.w;
        }
        __syncthreads();

#pragma unroll
        for (int kk = 0; kk < BK; kk++) {
            float4 a0 = *(const float4*)&As[kk][ty * 8];
            float4 a1 = *(const float4*)&As[kk][ty * 8 + 4];
            float4 w0 = *(const float4*)&Ws[kk][tx * 8];
            float4 w1 = *(const float4*)&Ws[kk][tx * 8 + 4];
            u64 ap0 = pack2(a0.x, a0.y), ap1 = pack2(a0.z, a0.w);
            u64 ap2 = pack2(a1.x, a1.y), ap3 = pack2(a1.z, a1.w);
            float wv[8] = {w0.x, w0.y, w0.z, w0.w, w1.x, w1.y, w1.z, w1.w};
#pragma unroll
            for (int j = 0; j < 8; j++) {
                u64 wd = pack2(wv[j], wv[j]);
                fma2(acc[0][j], ap0, wd);
                fma2(acc[1][j], ap1, wd);
                fma2(acc[2][j], ap2, wd);
                fma2(acc[3][j], ap3, wd);
            }
        }
        __syncthreads();
    }

#pragma unroll
    for (int ip = 0; ip < 4; ip++) {
        int gmA = m0 + ty * 8 + ip * 2;
        int gmB = gmA + 1;
#pragma unroll
        for (int j = 0; j < 8; j++) {
            int gn = n0 + tx * 8 + j;
            float2 v = unpack2(acc[ip][j]);
            if (gmA < M) {
                float r = (v.x + bias[gn]) * scale;
                if (add_res) r += res[(size_t)gmA * N + gn];
                C[(size_t)gmA * N + gn] = r;
            }
            if (gmB < M) {
                float r = (v.y + bias[gn]) * scale;
                if (add_res) r += res[(size_t)gmB * N + gn];
                C[(size_t)gmB * N + gn] = r;
            }
        }
    }
}

// ---------------- attention ------------------------------------------------
// Block = (32-query chunk, head, batch); 128 threads = 4 warps x 8 queries.
// lane == head-dim. Scores & PV on FFMA2; probs via smem (no PV shuffles).
__global__ __launch_bounds__(128)
void attn_kernel(const float* __restrict__ Qs, const float* __restrict__ Kg,
                 const float* __restrict__ Vg, const int* __restrict__ offs,
                 float* __restrict__ ctx)
{
    const int chunk = blockIdx.x;
    const int h     = blockIdx.y;
    const int b     = blockIdx.z;
    const int t     = threadIdx.x;
    const int w     = t >> 5;
    const int lane  = t & 31;

    __shared__ float qsT[HEADDIM][36];   // [dim][query] (pairs along q)
    __shared__ float Kt[HEADDIM][65];    // [dim][key]
    __shared__ float Vs[64][33];         // [key][dim]
    __shared__ u64   Pt[64][18];         // [key][qpair] packed probs

    const int off0 = offs[b];
    const int len  = offs[b + 1] - off0;

    // load Q chunk transposed
#pragma unroll
    for (int r = 0; r < 2; r++) {
        int idx = t + r * 128;
        int row = idx >> 3;              // q 0..31
        int cg  = (idx & 7) * 4;
        int nq  = chunk * 32 + row;
        float4 v = make_float4(0.f, 0.f, 0.f, 0.f);
        if (nq < NQ)
            v = *(const float4*)(Qs + ((size_t)(b * NQ + nq)) * D_MODEL + h * HEADDIM + cg);
        qsT[cg + 0][row] = v.x; qsT[cg + 1][row] = v.y;
        qsT[cg + 2][row] = v.z; qsT[cg + 3][row] = v.w;
    }

    u64 o2[4] = {0ull, 0ull, 0ull, 0ull};   // (q even, q odd) output pairs
    u64 lp[4] = {0ull, 0ull, 0ull, 0ull};   // per-lane l pairs
    float m[8];
#pragma unroll
    for (int q = 0; q < 8; q++) m[q] = -INFINITY;

    const int qrow = w * 8;
    const int qp0  = w * 4;

    for (int kt = 0; kt < len; kt += 64) {
        __syncthreads();
        // load K (transposed) and V tiles
#pragma unroll
        for (int r = 0; r < 4; r++) {
            int idx = t + r * 128;
            int row = idx >> 3;          // key 0..63
            int cg  = (idx & 7) * 4;
            int key = kt + row;
            float4 kv = make_float4(0.f, 0.f, 0.f, 0.f);
            float4 vv = make_float4(0.f, 0.f, 0.f, 0.f);
            if (key < len) {
                size_t base = ((size_t)(off0 + key)) * D_MODEL + h * HEADDIM + cg;
                kv = *(const float4*)(Kg + base);
                vv = *(const float4*)(Vg + base);
            }
            Kt[cg + 0][row] = kv.x; Kt[cg + 1][row] = kv.y;
            Kt[cg + 2][row] = kv.z; Kt[cg + 3][row] = kv.w;
            Vs[row][cg + 0] = vv.x; Vs[row][cg + 1] = vv.y;
            Vs[row][cg + 2] = vv.z; Vs[row][cg + 3] = vv.w;
        }
        __syncthreads();

        // ---- QK^T: s pairs over adjacent queries, keys = lane / lane+32 ----
        u64 s0p[4] = {0ull, 0ull, 0ull, 0ull};
        u64 s1p[4] = {0ull, 0ull, 0ull, 0ull};
#pragma unroll 8
        for (int d = 0; d < HEADDIM; d++) {
            float k0 = Kt[d][lane];
            float k1 = Kt[d][lane + 32];
            u64 k0d = pack2(k0, k0);
            u64 k1d = pack2(k1, k1);
            float4 qa = *(const float4*)&qsT[d][qrow];
            float4 qb = *(const float4*)&qsT[d][qrow + 4];
            u64 q0 = pack2(qa.x, qa.y), q1 = pack2(qa.z, qa.w);
            u64 q2 = pack2(qb.x, qb.y), q3 = pack2(qb.z, qb.w);
            fma2(s0p[0], q0, k0d); fma2(s0p[1], q1, k0d);
            fma2(s0p[2], q2, k0d); fma2(s0p[3], q3, k0d);
            fma2(s1p[0], q0, k1d); fma2(s1p[1], q1, k1d);
            fma2(s1p[2], q2, k1d); fma2(s1p[3], q3, k1d);
        }

        const bool valid0 = (kt + lane) < len;
        const bool valid1 = (kt + 32 + lane) < len;

        float s0[8], s1[8];
#pragma unroll
        for (int qp = 0; qp < 4; qp++) {
            float2 v0 = unpack2(s0p[qp]); s0[2 * qp] = v0.x; s0[2 * qp + 1] = v0.y;
            float2 v1 = unpack2(s1p[qp]); s1[2 * qp] = v1.x; s1[2 * qp + 1] = v1.y;
        }

        // ---- online softmax (only max needs a warp reduction) ----
        float p0[8], p1[8], alpha[8];
#pragma unroll
        for (int q = 0; q < 8; q++) {
            float a  = valid0 ? s0[q] : -INFINITY;
            float bb = valid1 ? s1[q] : -INFINITY;
            float mx = fmaxf(a, bb);
#pragma unroll
            for (int o = 16; o; o >>= 1)
                mx = fmaxf(mx, __shfl_xor_sync(0xffffffffu, mx, o));
            float m_new = fmaxf(m[q], mx);
            p0[q] = __expf(a - m_new);
            p1[q] = __expf(bb - m_new);
            alpha[q] = __expf(m[q] - m_new);
            m[q] = m_new;
        }

#pragma unroll
        for (int qp = 0; qp < 4; qp++) {
            u64 pp0 = pack2(p0[2 * qp], p0[2 * qp + 1]);
            u64 pp1 = pack2(p1[2 * qp], p1[2 * qp + 1]);
            Pt[lane][qp0 + qp]      = pp0;
            Pt[lane + 32][qp0 + qp] = pp1;
            u64 ap = pack2(alpha[2 * qp], alpha[2 * qp + 1]);
            u64 ps = add2(pp0, pp1);
            fma2(ps, lp[qp], ap);            // ps = lp*alpha + (p0+p1)
            lp[qp] = ps;
            o2[qp] = mul2(o2[qp], ap);       // rescale running output
        }
        __syncwarp();

        // ---- PV: o[qpair][dim=lane] += P[k][qpair] * V[k][lane] ----
#pragma unroll 8
        for (int k = 0; k < 64; k++) {
            float v = Vs[k][lane];
            u64 vd = pack2(v, v);
            ulonglong2 pA = *(const ulonglong2*)&Pt[k][qp0];
            ulonglong2 pB = *(const ulonglong2*)&Pt[k][qp0 + 2];
            fma2(o2[0], pA.x, vd);
            fma2(o2[1], pA.y, vd);
            fma2(o2[2], pB.x, vd);
            fma2(o2[3], pB.y, vd);
        }
    }

    // ---- finalize: reduce l across lanes, divide, store ----
#pragma unroll
    for (int qp = 0; qp < 4; qp++) {
        float2 ov = unpack2(o2[qp]);
        float2 lv = unpack2(lp[qp]);
        float la = lv.x, lb = lv.y;
#pragma unroll
        for (int o = 16; o; o >>= 1) {
            la += __shfl_xor_sync(0xffffffffu, la, o);
            lb += __shfl_xor_sync(0xffffffffu, lb, o);
        }
        int nq0 = chunk * 32 + qrow + 2 * qp;
        if (nq0 < NQ)
            ctx[((size_t)(b * NQ + nq0)) * D_MODEL + h * HEADDIM + lane] =
                (la > 0.f) ? ov.x / la : 0.f;
        if (nq0 + 1 < NQ)
            ctx[((size_t)(b * NQ + nq0 + 1)) * D_MODEL + h * HEADDIM + lane] =
                (lb > 0.f) ? ov.y / lb : 0.f;
    }
}

// ---------------- launch -----------------------------------------------------
extern "C" void kernel_launch(void* const* d_in, const int* in_sizes, int n_in,
                              void* d_out, int out_size)
{
    const float* source = (const float*)d_in[0];
    const float* query  = (const float*)d_in[1];
    const int*   offs   = (const int*)  d_in[2];
    const float* Wq = (const float*)d_in[3];  const float* bq = (const float*)d_in[4];
    const float* Wk = (const float*)d_in[5];  const float* bk = (const float*)d_in[6];
    const float* Wv = (const float*)d_in[7];  const float* bv = (const float*)d_in[8];
    const float* Wo = (const float*)d_in[9];  const float* bo = (const float*)d_in[10];
    float* out = (float*)d_out;

    const int Ntok = in_sizes[0] / D_MODEL;
    const int B    = in_sizes[1] / (NQ * D_MODEL);
    const int Mq   = B * NQ;
    const float scale = 1.0f / sqrtf((float)HEADDIM);

    float *pK, *pV, *pQs, *pCtx;
    cudaGetSymbolAddress((void**)&pK,  g_K);
    cudaGetSymbolAddress((void**)&pV,  g_V);
    cudaGetSymbolAddress((void**)&pQs, g_Qs);
    cudaGetSymbolAddress((void**)&pCtx, g_ctx);

    dim3 blk(256);

    { // q projection (scaled)
        dim3 grid(D_MODEL / 128, (Mq + 127) / 128);
        gemm_bias_kernel<<<grid, blk>>>(query, Wq, bq, nullptr, pQs,
                                        Mq, D_MODEL, D_MODEL, scale, 0);
    }
    { // K projection
        dim3 grid(D_MODEL / 128, (Ntok + 127) / 128);
        gemm_bias_kernel<<<grid, blk>>>(source, Wk, bk, nullptr, pK,
                                        Ntok, D_MODEL, D_MODEL, 1.0f, 0);
    }
    { // V projection
        dim3 grid(D_MODEL / 128, (Ntok + 127) / 128);
        gemm_bias_kernel<<<grid, blk>>>(source, Wv, bv, nullptr, pV,
                                        Ntok, D_MODEL, D_MODEL, 1.0f, 0);
    }
    { // attention
        dim3 grid((NQ + 31) / 32, NHEAD, B);
        attn_kernel<<<grid, 128>>>(pQs, pK, pV, offs, pCtx);
    }
    { // out projection + bias + residual
        dim3 grid(D_MODEL / 128, (Mq + 127) / 128);
        gemm_bias_kernel<<<grid, blk>>>(pCtx, Wo, bo, query, out,
                                        Mq, D_MODEL, D_MODEL, 1.0f, 1);
    }
}